// round 4
// baseline (speedup 1.0000x reference)
#include <cuda_runtime.h>

// EdgeDecoder: out[e] = relu(concat(user[i], movie[j]) @ w1^T + b1) @ w2^T + b2
// Restructured:
//   U[i] = user_emb[i]  @ w1[:, :128]^T + b1   (precomputed, referenced rows only)
//   M[j] = movie_emb[j] @ w1[:, 128:]^T        (precomputed, referenced rows only)
//   out[e] = relu(U[i]+M[j]) . w2 + b2

#define HIDDEN      128
#define MAX_USERS   100000
#define MAX_MOVIES  50000
#define WT_STRIDE   132            // padded row stride for transposed w1 in smem
#define PRE_THREADS 256
#define ROWS_PER_WARP 8
#define SMEM_FLOATS (HIDDEN * WT_STRIDE + 8 * ROWS_PER_WARP * HIDDEN)

__device__ __align__(16) float g_U[(size_t)MAX_USERS  * HIDDEN];
__device__ __align__(16) float g_M[(size_t)MAX_MOVIES * HIDDEN];
__device__ int g_idx_is_i64;   // 1 if edge index buffer is int64, 0 if int32
__device__ int g_max_user;     // max referenced user index (exact)
__device__ int g_max_movie;    // max referenced movie index (exact)

__device__ __forceinline__ unsigned long long pack2(float x) {
    unsigned long long r;
    asm("mov.b64 %0, {%1, %1};" : "=l"(r) : "f"(x));
    return r;
}
__device__ __forceinline__ void ffma2(unsigned long long& acc,
                                      unsigned long long w,
                                      unsigned long long x) {
    asm("fma.rn.f32x2 %0, %1, %2, %0;" : "+l"(acc) : "l"(w), "l"(x));
}
__device__ __forceinline__ float2 unpack2(unsigned long long v) {
    float lo, hi;
    asm("mov.b64 {%0, %1}, %2;" : "=f"(lo), "=f"(hi) : "l"(v));
    return make_float2(lo, hi);
}

// ---------------------------------------------------------------------------
// Init+probe: decide int64 vs int32 view of the edge-index buffer, and zero
// the max accumulators. Little-endian int64 (values < 2^31) has all odd
// int32 words == 0; genuine int32 index data essentially never does.
// ---------------------------------------------------------------------------
__global__ void init_probe_kernel(const int* __restrict__ ei32)
{
    if (threadIdx.x == 0) {
        int all_zero = 1;
        #pragma unroll 8
        for (int k = 1; k < 256; k += 2)
            if (ei32[k] != 0) { all_zero = 0; break; }
        g_idx_is_i64 = all_zero;
        g_max_user   = 0;
        g_max_movie  = 0;
    }
}

// ---------------------------------------------------------------------------
// Exact max-index reduction over both index rows.
// ---------------------------------------------------------------------------
__global__ __launch_bounds__(256)
void reduce_max_kernel(const int* __restrict__ ei32, int E)
{
    __shared__ int s_u[8], s_m[8];
    const int mode64 = g_idx_is_i64;
    int tid  = blockIdx.x * blockDim.x + threadIdx.x;
    int nthr = gridDim.x * blockDim.x;

    int mu = 0, mm = 0;
    for (int e = tid; e < E; e += nthr) {
        int iu, im;
        if (mode64) { iu = ei32[2 * e]; im = ei32[2 * (E + e)]; }
        else        { iu = ei32[e];     im = ei32[E + e]; }
        mu = max(mu, iu);
        mm = max(mm, im);
    }
    #pragma unroll
    for (int o = 16; o > 0; o >>= 1) {
        mu = max(mu, __shfl_xor_sync(0xffffffffu, mu, o));
        mm = max(mm, __shfl_xor_sync(0xffffffffu, mm, o));
    }
    int warp = threadIdx.x >> 5, lane = threadIdx.x & 31;
    if (lane == 0) { s_u[warp] = mu; s_m[warp] = mm; }
    __syncthreads();
    if (threadIdx.x == 0) {
        int bu = s_u[0], bm = s_m[0];
        #pragma unroll
        for (int w = 1; w < 8; w++) { bu = max(bu, s_u[w]); bm = max(bm, s_m[w]); }
        atomicMax(&g_max_user, bu);
        atomicMax(&g_max_movie, bm);
    }
}

// ---------------------------------------------------------------------------
// Precompute kernel: blocks [0, g_user) do the user table (koff=0, +b1),
// blocks [g_user, grid) do the movie table (koff=128, no bias).
// Each warp handles 8 rows; lane l computes outputs j = 4l..4l+3 via packed
// f32x2 FMA. k processed in steps of 4 with LDS.128 for both weights and
// broadcast x (high FMA-per-crossbar-byte ratio).
// ---------------------------------------------------------------------------
__global__ __launch_bounds__(PRE_THREADS, 2)
void precompute_kernel(const float* __restrict__ user_emb,
                       const float* __restrict__ movie_emb,
                       const float* __restrict__ w1,
                       const float* __restrict__ b1,
                       int n_users, int n_movies, int g_user)
{
    extern __shared__ float smem[];
    float* wT = smem;                         // [128][WT_STRIDE]
    float* xs = smem + HIDDEN * WT_STRIDE;    // [8 warps][8 rows][128]

    const float* emb;
    float*       outT;
    int nrows, koff, addBias, bx, gsz;
    if ((int)blockIdx.x < g_user) {
        emb = user_emb;  outT = g_U;
        nrows = min(n_users, g_max_user + 1);
        koff = 0; addBias = 1;
        bx = blockIdx.x; gsz = g_user;
    } else {
        emb = movie_emb; outT = g_M;
        nrows = min(n_movies, g_max_movie + 1);
        koff = HIDDEN; addBias = 0;
        bx = blockIdx.x - g_user; gsz = gridDim.x - g_user;
    }

    // Stage the relevant 128x128 half of w1, transposed: wT[k][j] = w1[j][koff+k]
    for (int idx = threadIdx.x; idx < HIDDEN * HIDDEN; idx += PRE_THREADS) {
        int j = idx >> 7;               // output index
        int k = idx & (HIDDEN - 1);     // reduction index (coalesced gmem read)
        wT[k * WT_STRIDE + j] = w1[j * (2 * HIDDEN) + koff + k];
    }
    __syncthreads();

    int warp = threadIdx.x >> 5;
    int lane = threadIdx.x & 31;
    float* xw = xs + warp * (ROWS_PER_WARP * HIDDEN);

    float4 bias = make_float4(0.f, 0.f, 0.f, 0.f);
    if (addBias) bias = ((const float4*)b1)[lane];

    int ngroups = (nrows + ROWS_PER_WARP - 1) / ROWS_PER_WARP;
    for (int g = bx * 8 + warp; g < ngroups; g += gsz * 8) {
        int row0 = g * ROWS_PER_WARP;

        // stage 8 input rows (coalesced float4 loads)
        #pragma unroll
        for (int r = 0; r < ROWS_PER_WARP; r++) {
            int row = row0 + r;
            float4 v = make_float4(0.f, 0.f, 0.f, 0.f);
            if (row < nrows)
                v = ((const float4*)(emb + (size_t)row * HIDDEN))[lane];
            ((float4*)(xw + r * HIDDEN))[lane] = v;
        }
        __syncwarp();

        // accumulators: 8 rows x 2 packed pairs (cols 4l..4l+1, 4l+2..4l+3)
        unsigned long long a[ROWS_PER_WARP][2];
        #pragma unroll
        for (int r = 0; r < ROWS_PER_WARP; r++) { a[r][0] = 0ull; a[r][1] = 0ull; }

        const float* wrow = wT + 4 * lane;
        #pragma unroll 2
        for (int kk = 0; kk < HIDDEN; kk += 4) {
            ulonglong2 w[4];
            #pragma unroll
            for (int d = 0; d < 4; d++)
                w[d] = *(const ulonglong2*)(wrow + (kk + d) * WT_STRIDE);
            float4 xv[ROWS_PER_WARP];
            #pragma unroll
            for (int r = 0; r < ROWS_PER_WARP; r++)
                xv[r] = *(const float4*)(xw + r * HIDDEN + kk);

            #pragma unroll
            for (int r = 0; r < ROWS_PER_WARP; r++) {
                unsigned long long xp;
                xp = pack2(xv[r].x);
                ffma2(a[r][0], w[0].x, xp); ffma2(a[r][1], w[0].y, xp);
                xp = pack2(xv[r].y);
                ffma2(a[r][0], w[1].x, xp); ffma2(a[r][1], w[1].y, xp);
                xp = pack2(xv[r].z);
                ffma2(a[r][0], w[2].x, xp); ffma2(a[r][1], w[2].y, xp);
                xp = pack2(xv[r].w);
                ffma2(a[r][0], w[3].x, xp); ffma2(a[r][1], w[3].y, xp);
            }
        }

        #pragma unroll
        for (int r = 0; r < ROWS_PER_WARP; r++) {
            int row = row0 + r;
            if (row < nrows) {
                float2 lo = unpack2(a[r][0]);
                float2 hi = unpack2(a[r][1]);
                float4 o;
                o.x = lo.x + bias.x;
                o.y = lo.y + bias.y;
                o.z = hi.x + bias.z;
                o.w = hi.y + bias.w;
                ((float4*)(outT + (size_t)row * HIDDEN))[lane] = o;
            }
        }
        __syncwarp();   // protect xs before next iteration's restage
    }
}

// ---------------------------------------------------------------------------
// Edge kernel: 4 edges per warp, 8 lanes per edge. Each lane covers 16
// elements (4 float4 from U + 4 from M -> MLP=8 loads in flight). 3-stage
// xor-shfl reduce within the 8-lane group; sub-lane 0 writes the scalar.
// ---------------------------------------------------------------------------
__global__ __launch_bounds__(256)
void edge_kernel(const int* __restrict__ ei32,
                 const float* __restrict__ w2,
                 const float* __restrict__ b2,
                 float* __restrict__ out, int E,
                 int n_users, int n_movies)
{
    int lane = threadIdx.x & 31;
    int grp  = lane >> 3;          // which of 4 edges in this warp
    int sub  = lane & 7;           // element slice within the edge
    int warp = (int)((blockIdx.x * blockDim.x + threadIdx.x) >> 5);
    int nw   = (int)((gridDim.x * blockDim.x) >> 5);

    const int mode64 = g_idx_is_i64;
    float4 wv[4];
    #pragma unroll
    for (int c = 0; c < 4; c++) wv[c] = ((const float4*)w2)[sub * 4 + c];
    float bb = b2[0];
    const float4* U4 = (const float4*)g_U;
    const float4* M4 = (const float4*)g_M;

    for (int e0 = warp * 4; e0 < E; e0 += nw * 4) {
        int e = e0 + grp;
        int valid = e < E;
        int ecl = valid ? e : (E - 1);

        int iu, im;
        if (mode64) {
            iu = ei32[2 * ecl];              // low word of int64 edge[0][e]
            im = ei32[2 * (E + ecl)];        // low word of int64 edge[1][e]
        } else {
            iu = ei32[ecl];
            im = ei32[E + ecl];
        }
        // clamp: crash-proof regardless of dtype interpretation
        iu = min(max(iu, 0), n_users  - 1);
        im = min(max(im, 0), n_movies - 1);

        const float4* up = U4 + (size_t)iu * 32 + sub * 4;
        const float4* mp = M4 + (size_t)im * 32 + sub * 4;

        float s = 0.f;
        #pragma unroll
        for (int c = 0; c < 4; c++) {
            float4 u = up[c];
            float4 m = mp[c];
            s = fmaf(fmaxf(u.x + m.x, 0.f), wv[c].x, s);
            s = fmaf(fmaxf(u.y + m.y, 0.f), wv[c].y, s);
            s = fmaf(fmaxf(u.z + m.z, 0.f), wv[c].z, s);
            s = fmaf(fmaxf(u.w + m.w, 0.f), wv[c].w, s);
        }

        s += __shfl_xor_sync(0xffffffffu, s, 4);
        s += __shfl_xor_sync(0xffffffffu, s, 2);
        s += __shfl_xor_sync(0xffffffffu, s, 1);

        if (sub == 0 && valid) out[e] = s + bb;
    }
}

// ---------------------------------------------------------------------------
extern "C" void kernel_launch(void* const* d_in, const int* in_sizes, int n_in,
                              void* d_out, int out_size)
{
    const float* user_emb  = (const float*)d_in[0];
    const float* movie_emb = (const float*)d_in[1];
    const int*   ei32      = (const int*)d_in[2];
    const float* w1        = (const float*)d_in[3];
    const float* b1        = (const float*)d_in[4];
    const float* w2        = (const float*)d_in[5];
    const float* b2        = (const float*)d_in[6];
    float*       out       = (float*)d_out;

    int n_users  = in_sizes[0] / HIDDEN;
    int n_movies = in_sizes[1] / HIDDEN;
    if (n_users  > MAX_USERS)  n_users  = MAX_USERS;
    if (n_movies > MAX_MOVIES) n_movies = MAX_MOVIES;
    int E = out_size;                       // out is [E, 1]

    size_t smem_bytes = (size_t)SMEM_FLOATS * sizeof(float);   // 100352 B
    cudaFuncSetAttribute(precompute_kernel,
                         cudaFuncAttributeMaxDynamicSharedMemorySize,
                         (int)smem_bytes);

    init_probe_kernel<<<1, 32>>>(ei32);
    reduce_max_kernel<<<256, 256>>>(ei32, E);

    // 2 blocks/SM resident at ~98KB smem; both tables ~equal referenced rows.
    const int g_user = 296, g_movie = 296;
    precompute_kernel<<<g_user + g_movie, PRE_THREADS, smem_bytes>>>(
        user_emb, movie_emb, w1, b1, n_users, n_movies, g_user);

    edge_kernel<<<2048, 256>>>(ei32, w2, b2, out, E, n_users, n_movies);
}

// round 7
// speedup vs baseline: 1.1905x; 1.1905x over previous
#include <cuda_runtime.h>

// EdgeDecoder: out[e] = relu(concat(user[i], movie[j]) @ w1^T + b1) @ w2^T + b2
// Restructured:
//   U[i] = user_emb[i]  @ w1[:, :128]^T + b1   (precomputed, referenced rows only)
//   M[j] = movie_emb[j] @ w1[:, 128:]^T        (precomputed, referenced rows only)
//   out[e] = relu(U[i]+M[j]) . w2 + b2

#define HIDDEN      128
#define MAX_USERS   100000
#define MAX_MOVIES  50000
#define WT_STRIDE   132            // padded row stride for transposed w1 in smem
#define PRE_THREADS 128
#define PRE_WARPS   (PRE_THREADS / 32)
#define ROWS_PER_WARP 16
#define SMEM_FLOATS (HIDDEN * WT_STRIDE + PRE_WARPS * ROWS_PER_WARP * HIDDEN)

__device__ __align__(16) float g_U[(size_t)MAX_USERS  * HIDDEN];
__device__ __align__(16) float g_M[(size_t)MAX_MOVIES * HIDDEN];
__device__ int g_idx_is_i64;   // 1 if edge index buffer is int64, 0 if int32
__device__ int g_max_user;     // max referenced user index (exact)
__device__ int g_max_movie;    // max referenced movie index (exact)

__device__ __forceinline__ unsigned long long pack2(float x) {
    unsigned long long r;
    asm("mov.b64 %0, {%1, %1};" : "=l"(r) : "f"(x));
    return r;
}
__device__ __forceinline__ void ffma2(unsigned long long& acc,
                                      unsigned long long w,
                                      unsigned long long x) {
    asm("fma.rn.f32x2 %0, %1, %2, %0;" : "+l"(acc) : "l"(w), "l"(x));
}
__device__ __forceinline__ float2 unpack2(unsigned long long v) {
    float lo, hi;
    asm("mov.b64 {%0, %1}, %2;" : "=f"(lo), "=f"(hi) : "l"(v));
    return make_float2(lo, hi);
}

// ---------------------------------------------------------------------------
// Init+probe: decide int64 vs int32 view of the edge-index buffer, and zero
// the max accumulators. Little-endian int64 (values < 2^31) has all odd
// int32 words == 0; genuine int32 index data essentially never does.
// ---------------------------------------------------------------------------
__global__ void init_probe_kernel(const int* __restrict__ ei32)
{
    if (threadIdx.x == 0) {
        int all_zero = 1;
        #pragma unroll 8
        for (int k = 1; k < 256; k += 2)
            if (ei32[k] != 0) { all_zero = 0; break; }
        g_idx_is_i64 = all_zero;
        g_max_user   = 0;
        g_max_movie  = 0;
    }
}

// ---------------------------------------------------------------------------
// Exact max-index reduction over both index rows.
// ---------------------------------------------------------------------------
__global__ __launch_bounds__(256)
void reduce_max_kernel(const int* __restrict__ ei32, int E)
{
    __shared__ int s_u[8], s_m[8];
    const int mode64 = g_idx_is_i64;
    int tid  = blockIdx.x * blockDim.x + threadIdx.x;
    int nthr = gridDim.x * blockDim.x;

    int mu = 0, mm = 0;
    for (int e = tid; e < E; e += nthr) {
        int iu, im;
        if (mode64) { iu = ei32[2 * e]; im = ei32[2 * (E + e)]; }
        else        { iu = ei32[e];     im = ei32[E + e]; }
        mu = max(mu, iu);
        mm = max(mm, im);
    }
    #pragma unroll
    for (int o = 16; o > 0; o >>= 1) {
        mu = max(mu, __shfl_xor_sync(0xffffffffu, mu, o));
        mm = max(mm, __shfl_xor_sync(0xffffffffu, mm, o));
    }
    int warp = threadIdx.x >> 5, lane = threadIdx.x & 31;
    if (lane == 0) { s_u[warp] = mu; s_m[warp] = mm; }
    __syncthreads();
    if (threadIdx.x == 0) {
        int bu = s_u[0], bm = s_m[0];
        #pragma unroll
        for (int w = 1; w < 8; w++) { bu = max(bu, s_u[w]); bm = max(bm, s_m[w]); }
        atomicMax(&g_max_user, bu);
        atomicMax(&g_max_movie, bm);
    }
}

// ---------------------------------------------------------------------------
// Precompute kernel: blocks [0, g_user) do the user table (koff=0, +b1),
// blocks [g_user, grid) do the movie table (koff=128, no bias).
// Each warp handles 16 rows; lane l computes outputs j = 4l..4l+3 via packed
// f32x2 FMA. Per 4-k step: 4 weight LDS.128 feed 128 FFMA2 (issue-bound,
// crossbar well under cap). x reads are broadcasts (conflict-free).
// ---------------------------------------------------------------------------
__global__ __launch_bounds__(PRE_THREADS, 2)
void precompute_kernel(const float* __restrict__ user_emb,
                       const float* __restrict__ movie_emb,
                       const float* __restrict__ w1,
                       const float* __restrict__ b1,
                       int n_users, int n_movies, int g_user)
{
    extern __shared__ float smem[];
    float* wT = smem;                         // [128][WT_STRIDE]
    float* xs = smem + HIDDEN * WT_STRIDE;    // [PRE_WARPS][16 rows][128]

    const float* emb;
    float*       outT;
    int nrows, addBias, bx, gsz;
    if ((int)blockIdx.x < g_user) {
        emb = user_emb;  outT = g_U;
        nrows = min(n_users, g_max_user + 1);
        addBias = 1;
        bx = blockIdx.x; gsz = g_user;
    } else {
        emb = movie_emb; outT = g_M;
        nrows = min(n_movies, g_max_movie + 1);
        addBias = 0;
        bx = blockIdx.x - g_user; gsz = gridDim.x - g_user;
    }
    int koff = addBias ? 0 : HIDDEN;

    // Stage the relevant 128x128 half of w1, transposed: wT[k][j] = w1[j][koff+k]
    for (int idx = threadIdx.x; idx < HIDDEN * HIDDEN; idx += PRE_THREADS) {
        int j = idx >> 7;               // output index
        int k = idx & (HIDDEN - 1);     // reduction index (coalesced gmem read)
        wT[k * WT_STRIDE + j] = w1[j * (2 * HIDDEN) + koff + k];
    }
    __syncthreads();

    int warp = threadIdx.x >> 5;
    int lane = threadIdx.x & 31;
    float* xw = xs + warp * (ROWS_PER_WARP * HIDDEN);

    float4 bias = make_float4(0.f, 0.f, 0.f, 0.f);
    if (addBias) bias = ((const float4*)b1)[lane];

    int ngroups = (nrows + ROWS_PER_WARP - 1) / ROWS_PER_WARP;
    for (int g = bx * PRE_WARPS + warp; g < ngroups; g += gsz * PRE_WARPS) {
        int row0 = g * ROWS_PER_WARP;

        // stage 16 input rows (coalesced float4 loads)
        #pragma unroll
        for (int r = 0; r < ROWS_PER_WARP; r++) {
            int row = row0 + r;
            float4 v = make_float4(0.f, 0.f, 0.f, 0.f);
            if (row < nrows)
                v = ((const float4*)(emb + (size_t)row * HIDDEN))[lane];
            ((float4*)(xw + r * HIDDEN))[lane] = v;
        }
        __syncwarp();

        // accumulators: 16 rows x 2 packed pairs (cols 4l..4l+1, 4l+2..4l+3)
        unsigned long long a[ROWS_PER_WARP][2];
        #pragma unroll
        for (int r = 0; r < ROWS_PER_WARP; r++) { a[r][0] = 0ull; a[r][1] = 0ull; }

        const float* wrow = wT + 4 * lane;
        for (int kk = 0; kk < HIDDEN; kk += 4) {
            ulonglong2 w[4];
            #pragma unroll
            for (int d = 0; d < 4; d++)
                w[d] = *(const ulonglong2*)(wrow + (kk + d) * WT_STRIDE);

            #pragma unroll
            for (int r = 0; r < ROWS_PER_WARP; r++) {
                float4 xv = *(const float4*)(xw + r * HIDDEN + kk);
                unsigned long long xp;
                xp = pack2(xv.x);
                ffma2(a[r][0], w[0].x, xp); ffma2(a[r][1], w[0].y, xp);
                xp = pack2(xv.y);
                ffma2(a[r][0], w[1].x, xp); ffma2(a[r][1], w[1].y, xp);
                xp = pack2(xv.z);
                ffma2(a[r][0], w[2].x, xp); ffma2(a[r][1], w[2].y, xp);
                xp = pack2(xv.w);
                ffma2(a[r][0], w[3].x, xp); ffma2(a[r][1], w[3].y, xp);
            }
        }

        #pragma unroll
        for (int r = 0; r < ROWS_PER_WARP; r++) {
            int row = row0 + r;
            if (row < nrows) {
                float2 lo = unpack2(a[r][0]);
                float2 hi = unpack2(a[r][1]);
                float4 o;
                o.x = lo.x + bias.x;
                o.y = lo.y + bias.y;
                o.z = hi.x + bias.z;
                o.w = hi.y + bias.w;
                ((float4*)(outT + (size_t)row * HIDDEN))[lane] = o;
            }
        }
        __syncwarp();   // protect xs before next iteration's restage
    }
}

// ---------------------------------------------------------------------------
// Edge kernel: one warp per edge row (full 512B coalesced row reads), TWO
// edges per iteration with interleaved chains: 4 row-LDGs in flight, the two
// 5-stage shfl reduction chains overlap. Lane l holds elements 4l..4l+3.
// ---------------------------------------------------------------------------
__global__ __launch_bounds__(256)
void edge_kernel(const int* __restrict__ ei32,
                 const float* __restrict__ w2,
                 const float* __restrict__ b2,
                 float* __restrict__ out, int E,
                 int n_users, int n_movies)
{
    int lane = threadIdx.x & 31;
    int warp = (int)((blockIdx.x * blockDim.x + threadIdx.x) >> 5);
    int nw   = (int)((gridDim.x * blockDim.x) >> 5);

    const int mode64 = g_idx_is_i64;
    float4 wv = ((const float4*)w2)[lane];
    float  bb = b2[0];
    const float4* U4 = (const float4*)g_U;
    const float4* M4 = (const float4*)g_M;

    for (int e0 = warp * 2; e0 < E; e0 += nw * 2) {
        int e1 = e0;
        int e2 = e0 + 1;
        int v2 = e2 < E;
        int e2c = v2 ? e2 : e1;

        int iu1, im1, iu2, im2;
        if (mode64) {
            iu1 = ei32[2 * e1];        im1 = ei32[2 * (E + e1)];
            iu2 = ei32[2 * e2c];       im2 = ei32[2 * (E + e2c)];
        } else {
            iu1 = ei32[e1];            im1 = ei32[E + e1];
            iu2 = ei32[e2c];           im2 = ei32[E + e2c];
        }
        // clamp: crash-proof regardless of dtype interpretation
        iu1 = min(max(iu1, 0), n_users  - 1);
        im1 = min(max(im1, 0), n_movies - 1);
        iu2 = min(max(iu2, 0), n_users  - 1);
        im2 = min(max(im2, 0), n_movies - 1);

        // 4 independent 512B coalesced row loads in flight
        float4 u1 = U4[(size_t)iu1 * 32 + lane];
        float4 m1 = M4[(size_t)im1 * 32 + lane];
        float4 u2 = U4[(size_t)iu2 * 32 + lane];
        float4 m2 = M4[(size_t)im2 * 32 + lane];

        float s1, s2;
        s1 = fmaxf(u1.x + m1.x, 0.f) * wv.x;
        s2 = fmaxf(u2.x + m2.x, 0.f) * wv.x;
        s1 = fmaf(fmaxf(u1.y + m1.y, 0.f), wv.y, s1);
        s2 = fmaf(fmaxf(u2.y + m2.y, 0.f), wv.y, s2);
        s1 = fmaf(fmaxf(u1.z + m1.z, 0.f), wv.z, s1);
        s2 = fmaf(fmaxf(u2.z + m2.z, 0.f), wv.z, s2);
        s1 = fmaf(fmaxf(u1.w + m1.w, 0.f), wv.w, s1);
        s2 = fmaf(fmaxf(u2.w + m2.w, 0.f), wv.w, s2);

        // interleaved butterfly reductions (independent chains overlap)
        s1 += __shfl_xor_sync(0xffffffffu, s1, 16);
        s2 += __shfl_xor_sync(0xffffffffu, s2, 16);
        s1 += __shfl_xor_sync(0xffffffffu, s1, 8);
        s2 += __shfl_xor_sync(0xffffffffu, s2, 8);
        s1 += __shfl_xor_sync(0xffffffffu, s1, 4);
        s2 += __shfl_xor_sync(0xffffffffu, s2, 4);
        s1 += __shfl_xor_sync(0xffffffffu, s1, 2);
        s2 += __shfl_xor_sync(0xffffffffu, s2, 2);
        s1 += __shfl_xor_sync(0xffffffffu, s1, 1);
        s2 += __shfl_xor_sync(0xffffffffu, s2, 1);

        if (lane == 0) {
            out[e1] = s1 + bb;
            if (v2) out[e2] = s2 + bb;
        }
    }
}

// ---------------------------------------------------------------------------
extern "C" void kernel_launch(void* const* d_in, const int* in_sizes, int n_in,
                              void* d_out, int out_size)
{
    const float* user_emb  = (const float*)d_in[0];
    const float* movie_emb = (const float*)d_in[1];
    const int*   ei32      = (const int*)d_in[2];
    const float* w1        = (const float*)d_in[3];
    const float* b1        = (const float*)d_in[4];
    const float* w2        = (const float*)d_in[5];
    const float* b2        = (const float*)d_in[6];
    float*       out       = (float*)d_out;

    int n_users  = in_sizes[0] / HIDDEN;
    int n_movies = in_sizes[1] / HIDDEN;
    if (n_users  > MAX_USERS)  n_users  = MAX_USERS;
    if (n_movies > MAX_MOVIES) n_movies = MAX_MOVIES;
    int E = out_size;                       // out is [E, 1]

    size_t smem_bytes = (size_t)SMEM_FLOATS * sizeof(float);   // 100352 B
    cudaFuncSetAttribute(precompute_kernel,
                         cudaFuncAttributeMaxDynamicSharedMemorySize,
                         (int)smem_bytes);

    init_probe_kernel<<<1, 32>>>(ei32);
    reduce_max_kernel<<<256, 256>>>(ei32, E);

    // 2 blocks/SM at ~98KB smem, 128 threads each; equal split user/movie.
    const int g_user = 148, g_movie = 148;
    precompute_kernel<<<g_user + g_movie, PRE_THREADS, smem_bytes>>>(
        user_emb, movie_emb, w1, b1, n_users, n_movies, g_user);

    edge_kernel<<<2048, 256>>>(ei32, w2, b2, out, E, n_users, n_movies);
}

// round 9
// speedup vs baseline: 1.3016x; 1.0933x over previous
#include <cuda_runtime.h>

// EdgeDecoder: out[e] = relu(concat(user[i], movie[j]) @ w1^T + b1) @ w2^T + b2
// Restructured:
//   U[i] = user_emb[i]  @ w1[:, :128]^T + b1   (precomputed, referenced rows only)
//   M[j] = movie_emb[j] @ w1[:, 128:]^T        (precomputed, referenced rows only)
//   out[e] = relu(U[i]+M[j]) . w2 + b2

#define HIDDEN      128
#define MAX_USERS   100000
#define MAX_MOVIES  50000
#define WT_STRIDE   132            // padded row stride for transposed w1 in smem
#define PRE_THREADS 256
#define ROWS_PER_WARP 8
#define SMEM_FLOATS (HIDDEN * WT_STRIDE + 8 * ROWS_PER_WARP * HIDDEN)

__device__ __align__(16) float g_U[(size_t)MAX_USERS  * HIDDEN];
__device__ __align__(16) float g_M[(size_t)MAX_MOVIES * HIDDEN];
__device__ int g_idx_is_i64;   // 1 if edge index buffer is int64, 0 if int32
__device__ int g_max_user;     // max referenced user index (exact)
__device__ int g_max_movie;    // max referenced movie index (exact)

__device__ __forceinline__ unsigned long long pack2(float x) {
    unsigned long long r;
    asm("mov.b64 %0, {%1, %1};" : "=l"(r) : "f"(x));
    return r;
}
__device__ __forceinline__ void ffma2(unsigned long long& acc,
                                      unsigned long long w,
                                      unsigned long long x) {
    asm("fma.rn.f32x2 %0, %1, %2, %0;" : "+l"(acc) : "l"(w), "l"(x));
}
__device__ __forceinline__ float2 unpack2(unsigned long long v) {
    float lo, hi;
    asm("mov.b64 {%0, %1}, %2;" : "=f"(lo), "=f"(hi) : "l"(v));
    return make_float2(lo, hi);
}

// ---------------------------------------------------------------------------
// Init+probe: decide int64 vs int32 view of the edge-index buffer, and zero
// the max accumulators. Little-endian int64 (values < 2^31) has all odd
// int32 words == 0; genuine int32 index data essentially never does.
// ---------------------------------------------------------------------------
__global__ void init_probe_kernel(const int* __restrict__ ei32)
{
    if (threadIdx.x == 0) {
        int all_zero = 1;
        #pragma unroll 8
        for (int k = 1; k < 256; k += 2)
            if (ei32[k] != 0) { all_zero = 0; break; }
        g_idx_is_i64 = all_zero;
        g_max_user   = 0;
        g_max_movie  = 0;
    }
}

// ---------------------------------------------------------------------------
// Exact max-index reduction over both index rows.
// ---------------------------------------------------------------------------
__global__ __launch_bounds__(256)
void reduce_max_kernel(const int* __restrict__ ei32, int E)
{
    __shared__ int s_u[8], s_m[8];
    const int mode64 = g_idx_is_i64;
    int tid  = blockIdx.x * blockDim.x + threadIdx.x;
    int nthr = gridDim.x * blockDim.x;

    int mu = 0, mm = 0;
    for (int e = tid; e < E; e += nthr) {
        int iu, im;
        if (mode64) { iu = ei32[2 * e]; im = ei32[2 * (E + e)]; }
        else        { iu = ei32[e];     im = ei32[E + e]; }
        mu = max(mu, iu);
        mm = max(mm, im);
    }
    #pragma unroll
    for (int o = 16; o > 0; o >>= 1) {
        mu = max(mu, __shfl_xor_sync(0xffffffffu, mu, o));
        mm = max(mm, __shfl_xor_sync(0xffffffffu, mm, o));
    }
    int warp = threadIdx.x >> 5, lane = threadIdx.x & 31;
    if (lane == 0) { s_u[warp] = mu; s_m[warp] = mm; }
    __syncthreads();
    if (threadIdx.x == 0) {
        int bu = s_u[0], bm = s_m[0];
        #pragma unroll
        for (int w = 1; w < 8; w++) { bu = max(bu, s_u[w]); bm = max(bm, s_m[w]); }
        atomicMax(&g_max_user, bu);
        atomicMax(&g_max_movie, bm);
    }
}

// ---------------------------------------------------------------------------
// Precompute kernel (measured-best config: 256 thr, 8 rows/warp, 4-k steps).
// Blocks [0, g_user) do the user table (+b1), rest do the movie table.
// Lane l computes outputs j = 4l..4l+3 via packed f32x2 FMA.
// ---------------------------------------------------------------------------
__global__ __launch_bounds__(PRE_THREADS, 2)
void precompute_kernel(const float* __restrict__ user_emb,
                       const float* __restrict__ movie_emb,
                       const float* __restrict__ w1,
                       const float* __restrict__ b1,
                       int n_users, int n_movies, int g_user)
{
    extern __shared__ float smem[];
    float* wT = smem;                         // [128][WT_STRIDE]
    float* xs = smem + HIDDEN * WT_STRIDE;    // [8 warps][8 rows][128]

    const float* emb;
    float*       outT;
    int nrows, addBias, bx, gsz;
    if ((int)blockIdx.x < g_user) {
        emb = user_emb;  outT = g_U;
        nrows = min(n_users, g_max_user + 1);
        addBias = 1;
        bx = blockIdx.x; gsz = g_user;
    } else {
        emb = movie_emb; outT = g_M;
        nrows = min(n_movies, g_max_movie + 1);
        addBias = 0;
        bx = blockIdx.x - g_user; gsz = gridDim.x - g_user;
    }
    int koff = addBias ? 0 : HIDDEN;

    // Stage the relevant 128x128 half of w1, transposed: wT[k][j] = w1[j][koff+k]
    for (int idx = threadIdx.x; idx < HIDDEN * HIDDEN; idx += PRE_THREADS) {
        int j = idx >> 7;               // output index
        int k = idx & (HIDDEN - 1);     // reduction index (coalesced gmem read)
        wT[k * WT_STRIDE + j] = w1[j * (2 * HIDDEN) + koff + k];
    }
    __syncthreads();

    int warp = threadIdx.x >> 5;
    int lane = threadIdx.x & 31;
    float* xw = xs + warp * (ROWS_PER_WARP * HIDDEN);

    float4 bias = make_float4(0.f, 0.f, 0.f, 0.f);
    if (addBias) bias = ((const float4*)b1)[lane];

    int ngroups = (nrows + ROWS_PER_WARP - 1) / ROWS_PER_WARP;
    for (int g = bx * 8 + warp; g < ngroups; g += gsz * 8) {
        int row0 = g * ROWS_PER_WARP;

        // stage 8 input rows (coalesced float4 loads)
        #pragma unroll
        for (int r = 0; r < ROWS_PER_WARP; r++) {
            int row = row0 + r;
            float4 v = make_float4(0.f, 0.f, 0.f, 0.f);
            if (row < nrows)
                v = ((const float4*)(emb + (size_t)row * HIDDEN))[lane];
            ((float4*)(xw + r * HIDDEN))[lane] = v;
        }
        __syncwarp();

        // accumulators: 8 rows x 2 packed pairs (cols 4l..4l+1, 4l+2..4l+3)
        unsigned long long a[ROWS_PER_WARP][2];
        #pragma unroll
        for (int r = 0; r < ROWS_PER_WARP; r++) { a[r][0] = 0ull; a[r][1] = 0ull; }

        const float* wrow = wT + 4 * lane;
        #pragma unroll 2
        for (int kk = 0; kk < HIDDEN; kk += 4) {
            ulonglong2 w[4];
            #pragma unroll
            for (int d = 0; d < 4; d++)
                w[d] = *(const ulonglong2*)(wrow + (kk + d) * WT_STRIDE);
            float4 xv[ROWS_PER_WARP];
            #pragma unroll
            for (int r = 0; r < ROWS_PER_WARP; r++)
                xv[r] = *(const float4*)(xw + r * HIDDEN + kk);

            #pragma unroll
            for (int r = 0; r < ROWS_PER_WARP; r++) {
                unsigned long long xp;
                xp = pack2(xv[r].x);
                ffma2(a[r][0], w[0].x, xp); ffma2(a[r][1], w[0].y, xp);
                xp = pack2(xv[r].y);
                ffma2(a[r][0], w[1].x, xp); ffma2(a[r][1], w[1].y, xp);
                xp = pack2(xv[r].z);
                ffma2(a[r][0], w[2].x, xp); ffma2(a[r][1], w[2].y, xp);
                xp = pack2(xv[r].w);
                ffma2(a[r][0], w[3].x, xp); ffma2(a[r][1], w[3].y, xp);
            }
        }

        #pragma unroll
        for (int r = 0; r < ROWS_PER_WARP; r++) {
            int row = row0 + r;
            if (row < nrows) {
                float2 lo = unpack2(a[r][0]);
                float2 hi = unpack2(a[r][1]);
                float4 o;
                o.x = lo.x + bias.x;
                o.y = lo.y + bias.y;
                o.z = hi.x + bias.z;
                o.w = hi.y + bias.w;
                ((float4*)(outT + (size_t)row * HIDDEN))[lane] = o;
            }
        }
        __syncwarp();   // protect xs before next iteration's restage
    }
}

// ---------------------------------------------------------------------------
// Edge kernel: one warp per edge row (full 512B coalesced row reads), TWO
// edges per iteration (4 row-LDGs in flight). Fused dual reduction: one
// xor-16 stage per edge, then lanes 0-15 carry edge1 / lanes 16-31 carry
// edge2 through 4 shared butterfly stages (6 shfls total instead of 10).
// ---------------------------------------------------------------------------
__global__ __launch_bounds__(256)
void edge_kernel(const int* __restrict__ ei32,
                 const float* __restrict__ w2,
                 const float* __restrict__ b2,
                 float* __restrict__ out, int E,
                 int n_users, int n_movies)
{
    int lane = threadIdx.x & 31;
    int warp = (int)((blockIdx.x * blockDim.x + threadIdx.x) >> 5);
    int nw   = (int)((gridDim.x * blockDim.x) >> 5);

    const int mode64 = g_idx_is_i64;
    float4 wv = ((const float4*)w2)[lane];
    float  bb = b2[0];
    const float4* U4 = (const float4*)g_U;
    const float4* M4 = (const float4*)g_M;
    const bool hi_half = (lane & 16) != 0;

    for (int e0 = warp * 2; e0 < E; e0 += nw * 2) {
        int e1 = e0;
        int e2 = e0 + 1;
        int v2 = e2 < E;
        int e2c = v2 ? e2 : e1;

        int iu1, im1, iu2, im2;
        if (mode64) {
            iu1 = ei32[2 * e1];        im1 = ei32[2 * (E + e1)];
            iu2 = ei32[2 * e2c];       im2 = ei32[2 * (E + e2c)];
        } else {
            iu1 = ei32[e1];            im1 = ei32[E + e1];
            iu2 = ei32[e2c];           im2 = ei32[E + e2c];
        }
        // clamp: crash-proof regardless of dtype interpretation
        iu1 = min(max(iu1, 0), n_users  - 1);
        im1 = min(max(im1, 0), n_movies - 1);
        iu2 = min(max(iu2, 0), n_users  - 1);
        im2 = min(max(im2, 0), n_movies - 1);

        // 4 independent 512B coalesced row loads in flight
        float4 u1 = U4[(size_t)iu1 * 32 + lane];
        float4 m1 = M4[(size_t)im1 * 32 + lane];
        float4 u2 = U4[(size_t)iu2 * 32 + lane];
        float4 m2 = M4[(size_t)im2 * 32 + lane];

        float s1, s2;
        s1 = fmaxf(u1.x + m1.x, 0.f) * wv.x;
        s2 = fmaxf(u2.x + m2.x, 0.f) * wv.x;
        s1 = fmaf(fmaxf(u1.y + m1.y, 0.f), wv.y, s1);
        s2 = fmaf(fmaxf(u2.y + m2.y, 0.f), wv.y, s2);
        s1 = fmaf(fmaxf(u1.z + m1.z, 0.f), wv.z, s1);
        s2 = fmaf(fmaxf(u2.z + m2.z, 0.f), wv.z, s2);
        s1 = fmaf(fmaxf(u1.w + m1.w, 0.f), wv.w, s1);
        s2 = fmaf(fmaxf(u2.w + m2.w, 0.f), wv.w, s2);

        // fused dual reduction: stage 16 separately, then merge halves
        s1 += __shfl_xor_sync(0xffffffffu, s1, 16);
        s2 += __shfl_xor_sync(0xffffffffu, s2, 16);
        float t = hi_half ? s2 : s1;
        t += __shfl_xor_sync(0xffffffffu, t, 8);
        t += __shfl_xor_sync(0xffffffffu, t, 4);
        t += __shfl_xor_sync(0xffffffffu, t, 2);
        t += __shfl_xor_sync(0xffffffffu, t, 1);
        // lane 0 holds edge1 sum; lane 16 holds edge2 sum

        if (lane == 0)       out[e1] = t + bb;
        if (lane == 16 && v2) out[e2] = t + bb;
    }
}

// ---------------------------------------------------------------------------
extern "C" void kernel_launch(void* const* d_in, const int* in_sizes, int n_in,
                              void* d_out, int out_size)
{
    const float* user_emb  = (const float*)d_in[0];
    const float* movie_emb = (const float*)d_in[1];
    const int*   ei32      = (const int*)d_in[2];
    const float* w1        = (const float*)d_in[3];
    const float* b1        = (const float*)d_in[4];
    const float* w2        = (const float*)d_in[5];
    const float* b2        = (const float*)d_in[6];
    float*       out       = (float*)d_out;

    int n_users  = in_sizes[0] / HIDDEN;
    int n_movies = in_sizes[1] / HIDDEN;
    if (n_users  > MAX_USERS)  n_users  = MAX_USERS;
    if (n_movies > MAX_MOVIES) n_movies = MAX_MOVIES;
    int E = out_size;                       // out is [E, 1]

    size_t smem_bytes = (size_t)SMEM_FLOATS * sizeof(float);   // 100352 B
    cudaFuncSetAttribute(precompute_kernel,
                         cudaFuncAttributeMaxDynamicSharedMemorySize,
                         (int)smem_bytes);

    init_probe_kernel<<<1, 32>>>(ei32);
    reduce_max_kernel<<<256, 256>>>(ei32, E);

    // 2 blocks/SM at ~98KB smem, 256 threads: 592 blocks = exactly resident.
    const int g_user = 296, g_movie = 296;
    precompute_kernel<<<g_user + g_movie, PRE_THREADS, smem_bytes>>>(
        user_emb, movie_emb, w1, b1, n_users, n_movies, g_user);

    edge_kernel<<<2048, 256>>>(ei32, w2, b2, out, E, n_users, n_movies);
}

// round 12
// speedup vs baseline: 1.4423x; 1.1081x over previous
#include <cuda_runtime.h>
#include <cuda_fp16.h>

// EdgeDecoder: out[e] = relu(concat(user[i], movie[j]) @ w1^T + b1) @ w2^T + b2
// Restructured:
//   U[i] = user_emb[i]  @ w1[:, :128]^T + b1   (precomputed, fp16 table)
//   M[j] = movie_emb[j] @ w1[:, 128:]^T        (precomputed, fp16 table)
//   out[e] = relu(U[i]+M[j]) . w2 + b2
// fp16 tables halve edge-phase memory traffic; storage error ~2^-11 per
// element aggregates to ~1e-5 final rel_err (threshold 1e-3).

#define HIDDEN      128
#define MAX_USERS   100000
#define MAX_MOVIES  50000
#define WT_STRIDE   132            // padded row stride for transposed w1 in smem
#define PRE_THREADS 256
#define ROWS_PER_WARP 8
#define SMEM_FLOATS (HIDDEN * WT_STRIDE + 8 * ROWS_PER_WARP * HIDDEN)

__device__ __align__(16) __half g_U[(size_t)MAX_USERS  * HIDDEN];
__device__ __align__(16) __half g_M[(size_t)MAX_MOVIES * HIDDEN];
__device__ int g_idx_is_i64;   // 1 if edge index buffer is int64, 0 if int32
__device__ int g_max_user;     // max referenced user index (exact)
__device__ int g_max_movie;    // max referenced movie index (exact)

__device__ __forceinline__ unsigned long long pack2(float x) {
    unsigned long long r;
    asm("mov.b64 %0, {%1, %1};" : "=l"(r) : "f"(x));
    return r;
}
__device__ __forceinline__ void ffma2(unsigned long long& acc,
                                      unsigned long long w,
                                      unsigned long long x) {
    asm("fma.rn.f32x2 %0, %1, %2, %0;" : "+l"(acc) : "l"(w), "l"(x));
}
__device__ __forceinline__ float2 unpack2(unsigned long long v) {
    float lo, hi;
    asm("mov.b64 {%0, %1}, %2;" : "=f"(lo), "=f"(hi) : "l"(v));
    return make_float2(lo, hi);
}

// ---------------------------------------------------------------------------
// Init+probe: decide int64 vs int32 view of the edge-index buffer, and zero
// the max accumulators.
// ---------------------------------------------------------------------------
__global__ void init_probe_kernel(const int* __restrict__ ei32)
{
    if (threadIdx.x == 0) {
        int all_zero = 1;
        #pragma unroll 8
        for (int k = 1; k < 256; k += 2)
            if (ei32[k] != 0) { all_zero = 0; break; }
        g_idx_is_i64 = all_zero;
        g_max_user   = 0;
        g_max_movie  = 0;
    }
}

// ---------------------------------------------------------------------------
// Exact max-index reduction over both index rows.
// ---------------------------------------------------------------------------
__global__ __launch_bounds__(256)
void reduce_max_kernel(const int* __restrict__ ei32, int E)
{
    __shared__ int s_u[8], s_m[8];
    const int mode64 = g_idx_is_i64;
    int tid  = blockIdx.x * blockDim.x + threadIdx.x;
    int nthr = gridDim.x * blockDim.x;

    int mu = 0, mm = 0;
    for (int e = tid; e < E; e += nthr) {
        int iu, im;
        if (mode64) { iu = ei32[2 * e]; im = ei32[2 * (E + e)]; }
        else        { iu = ei32[e];     im = ei32[E + e]; }
        mu = max(mu, iu);
        mm = max(mm, im);
    }
    #pragma unroll
    for (int o = 16; o > 0; o >>= 1) {
        mu = max(mu, __shfl_xor_sync(0xffffffffu, mu, o));
        mm = max(mm, __shfl_xor_sync(0xffffffffu, mm, o));
    }
    int warp = threadIdx.x >> 5, lane = threadIdx.x & 31;
    if (lane == 0) { s_u[warp] = mu; s_m[warp] = mm; }
    __syncthreads();
    if (threadIdx.x == 0) {
        int bu = s_u[0], bm = s_m[0];
        #pragma unroll
        for (int w = 1; w < 8; w++) { bu = max(bu, s_u[w]); bm = max(bm, s_m[w]); }
        atomicMax(&g_max_user, bu);
        atomicMax(&g_max_movie, bm);
    }
}

// ---------------------------------------------------------------------------
// Precompute kernel (measured-best config: 256 thr, 8 rows/warp, 4-k steps).
// Lane l computes outputs j = 4l..4l+3 via packed f32x2 FMA; results stored
// as fp16 (rounded once at the end).
// ---------------------------------------------------------------------------
__global__ __launch_bounds__(PRE_THREADS, 2)
void precompute_kernel(const float* __restrict__ user_emb,
                       const float* __restrict__ movie_emb,
                       const float* __restrict__ w1,
                       const float* __restrict__ b1,
                       int n_users, int n_movies, int g_user)
{
    extern __shared__ float smem[];
    float* wT = smem;                         // [128][WT_STRIDE]
    float* xs = smem + HIDDEN * WT_STRIDE;    // [8 warps][8 rows][128]

    const float* emb;
    __half*      outT;
    int nrows, addBias, bx, gsz;
    if ((int)blockIdx.x < g_user) {
        emb = user_emb;  outT = g_U;
        nrows = min(n_users, g_max_user + 1);
        addBias = 1;
        bx = blockIdx.x; gsz = g_user;
    } else {
        emb = movie_emb; outT = g_M;
        nrows = min(n_movies, g_max_movie + 1);
        addBias = 0;
        bx = blockIdx.x - g_user; gsz = gridDim.x - g_user;
    }
    int koff = addBias ? 0 : HIDDEN;

    // Stage the relevant 128x128 half of w1, transposed: wT[k][j] = w1[j][koff+k]
    for (int idx = threadIdx.x; idx < HIDDEN * HIDDEN; idx += PRE_THREADS) {
        int j = idx >> 7;               // output index
        int k = idx & (HIDDEN - 1);     // reduction index (coalesced gmem read)
        wT[k * WT_STRIDE + j] = w1[j * (2 * HIDDEN) + koff + k];
    }
    __syncthreads();

    int warp = threadIdx.x >> 5;
    int lane = threadIdx.x & 31;
    float* xw = xs + warp * (ROWS_PER_WARP * HIDDEN);

    float4 bias = make_float4(0.f, 0.f, 0.f, 0.f);
    if (addBias) bias = ((const float4*)b1)[lane];

    int ngroups = (nrows + ROWS_PER_WARP - 1) / ROWS_PER_WARP;
    for (int g = bx * 8 + warp; g < ngroups; g += gsz * 8) {
        int row0 = g * ROWS_PER_WARP;

        // stage 8 input rows (coalesced float4 loads)
        #pragma unroll
        for (int r = 0; r < ROWS_PER_WARP; r++) {
            int row = row0 + r;
            float4 v = make_float4(0.f, 0.f, 0.f, 0.f);
            if (row < nrows)
                v = ((const float4*)(emb + (size_t)row * HIDDEN))[lane];
            ((float4*)(xw + r * HIDDEN))[lane] = v;
        }
        __syncwarp();

        // accumulators: 8 rows x 2 packed pairs (cols 4l..4l+1, 4l+2..4l+3)
        unsigned long long a[ROWS_PER_WARP][2];
        #pragma unroll
        for (int r = 0; r < ROWS_PER_WARP; r++) { a[r][0] = 0ull; a[r][1] = 0ull; }

        const float* wrow = wT + 4 * lane;
        #pragma unroll 2
        for (int kk = 0; kk < HIDDEN; kk += 4) {
            ulonglong2 w[4];
            #pragma unroll
            for (int d = 0; d < 4; d++)
                w[d] = *(const ulonglong2*)(wrow + (kk + d) * WT_STRIDE);
            float4 xv[ROWS_PER_WARP];
            #pragma unroll
            for (int r = 0; r < ROWS_PER_WARP; r++)
                xv[r] = *(const float4*)(xw + r * HIDDEN + kk);

            #pragma unroll
            for (int r = 0; r < ROWS_PER_WARP; r++) {
                unsigned long long xp;
                xp = pack2(xv[r].x);
                ffma2(a[r][0], w[0].x, xp); ffma2(a[r][1], w[0].y, xp);
                xp = pack2(xv[r].y);
                ffma2(a[r][0], w[1].x, xp); ffma2(a[r][1], w[1].y, xp);
                xp = pack2(xv[r].z);
                ffma2(a[r][0], w[2].x, xp); ffma2(a[r][1], w[2].y, xp);
                xp = pack2(xv[r].w);
                ffma2(a[r][0], w[3].x, xp); ffma2(a[r][1], w[3].y, xp);
            }
        }

        #pragma unroll
        for (int r = 0; r < ROWS_PER_WARP; r++) {
            int row = row0 + r;
            if (row < nrows) {
                float2 lo = unpack2(a[r][0]);
                float2 hi = unpack2(a[r][1]);
                __half2 h01 = __floats2half2_rn(lo.x + bias.x, lo.y + bias.y);
                __half2 h23 = __floats2half2_rn(hi.x + bias.z, hi.y + bias.w);
                uint2 st;
                st.x = *(unsigned int*)&h01;
                st.y = *(unsigned int*)&h23;
                ((uint2*)(outT + (size_t)row * HIDDEN))[lane] = st;
            }
        }
        __syncwarp();   // protect xs before next iteration's restage
    }
}

// ---------------------------------------------------------------------------
// Edge kernel: one warp per edge row (256B coalesced fp16 row reads, LDG.64
// per lane), TWO edges per iteration (4 row loads in flight). Fused dual
// shfl reduction (6 shfls for 2 edges). Lane l holds elements 4l..4l+3.
// ---------------------------------------------------------------------------
__global__ __launch_bounds__(256)
void edge_kernel(const int* __restrict__ ei32,
                 const float* __restrict__ w2,
                 const float* __restrict__ b2,
                 float* __restrict__ out, int E,
                 int n_users, int n_movies)
{
    int lane = threadIdx.x & 31;
    int warp = (int)((blockIdx.x * blockDim.x + threadIdx.x) >> 5);
    int nw   = (int)((gridDim.x * blockDim.x) >> 5);

    const int mode64 = g_idx_is_i64;
    float4 wv = ((const float4*)w2)[lane];
    float  bb = b2[0];
    const uint2* U2 = (const uint2*)g_U;   // row stride = 32 uint2 (256B)
    const uint2* M2 = (const uint2*)g_M;
    const bool hi_half = (lane & 16) != 0;
    const __half2 z2 = __float2half2_rn(0.f);

    for (int e0 = warp * 2; e0 < E; e0 += nw * 2) {
        int e1 = e0;
        int e2 = e0 + 1;
        int v2 = e2 < E;
        int e2c = v2 ? e2 : e1;

        int iu1, im1, iu2, im2;
        if (mode64) {
            iu1 = ei32[2 * e1];        im1 = ei32[2 * (E + e1)];
            iu2 = ei32[2 * e2c];       im2 = ei32[2 * (E + e2c)];
        } else {
            iu1 = ei32[e1];            im1 = ei32[E + e1];
            iu2 = ei32[e2c];           im2 = ei32[E + e2c];
        }
        iu1 = min(max(iu1, 0), n_users  - 1);
        im1 = min(max(im1, 0), n_movies - 1);
        iu2 = min(max(iu2, 0), n_users  - 1);
        im2 = min(max(im2, 0), n_movies - 1);

        uint2 ua = U2[(size_t)iu1 * 32 + lane];
        uint2 ma = M2[(size_t)im1 * 32 + lane];
        uint2 ub = U2[(size_t)iu2 * 32 + lane];
        uint2 mb = M2[(size_t)im2 * 32 + lane];

        // edge1: h = relu(u+m) in fp16, dot in fp32
        __half2 a01 = __hmax2(__hadd2(*(__half2*)&ua.x, *(__half2*)&ma.x), z2);
        __half2 a23 = __hmax2(__hadd2(*(__half2*)&ua.y, *(__half2*)&ma.y), z2);
        __half2 b01 = __hmax2(__hadd2(*(__half2*)&ub.x, *(__half2*)&mb.x), z2);
        __half2 b23 = __hmax2(__hadd2(*(__half2*)&ub.y, *(__half2*)&mb.y), z2);

        float2 fa01 = __half22float2(a01);
        float2 fa23 = __half22float2(a23);
        float2 fb01 = __half22float2(b01);
        float2 fb23 = __half22float2(b23);

        float s1, s2;
        s1 = fa01.x * wv.x;
        s2 = fb01.x * wv.x;
        s1 = fmaf(fa01.y, wv.y, s1);
        s2 = fmaf(fb01.y, wv.y, s2);
        s1 = fmaf(fa23.x, wv.z, s1);
        s2 = fmaf(fb23.x, wv.z, s2);
        s1 = fmaf(fa23.y, wv.w, s1);
        s2 = fmaf(fb23.y, wv.w, s2);

        // fused dual reduction: stage 16 separately, then merge halves
        s1 += __shfl_xor_sync(0xffffffffu, s1, 16);
        s2 += __shfl_xor_sync(0xffffffffu, s2, 16);
        float t = hi_half ? s2 : s1;
        t += __shfl_xor_sync(0xffffffffu, t, 8);
        t += __shfl_xor_sync(0xffffffffu, t, 4);
        t += __shfl_xor_sync(0xffffffffu, t, 2);
        t += __shfl_xor_sync(0xffffffffu, t, 1);
        // lane 0 holds edge1 sum; lane 16 holds edge2 sum

        if (lane == 0)        out[e1] = t + bb;
        if (lane == 16 && v2) out[e2] = t + bb;
    }
}

// ---------------------------------------------------------------------------
extern "C" void kernel_launch(void* const* d_in, const int* in_sizes, int n_in,
                              void* d_out, int out_size)
{
    const float* user_emb  = (const float*)d_in[0];
    const float* movie_emb = (const float*)d_in[1];
    const int*   ei32      = (const int*)d_in[2];
    const float* w1        = (const float*)d_in[3];
    const float* b1        = (const float*)d_in[4];
    const float* w2        = (const float*)d_in[5];
    const float* b2        = (const float*)d_in[6];
    float*       out       = (float*)d_out;

    int n_users  = in_sizes[0] / HIDDEN;
    int n_movies = in_sizes[1] / HIDDEN;
    if (n_users  > MAX_USERS)  n_users  = MAX_USERS;
    if (n_movies > MAX_MOVIES) n_movies = MAX_MOVIES;
    int E = out_size;                       // out is [E, 1]

    size_t smem_bytes = (size_t)SMEM_FLOATS * sizeof(float);   // 100352 B
    cudaFuncSetAttribute(precompute_kernel,
                         cudaFuncAttributeMaxDynamicSharedMemorySize,
                         (int)smem_bytes);

    init_probe_kernel<<<1, 32>>>(ei32);
    reduce_max_kernel<<<256, 256>>>(ei32, E);

    // 2 blocks/SM at ~98KB smem, 256 threads: 592 blocks = exactly resident.
    const int g_user = 296, g_movie = 296;
    precompute_kernel<<<g_user + g_movie, PRE_THREADS, smem_bytes>>>(
        user_emb, movie_emb, w1, b1, n_users, n_movies, g_user);

    edge_kernel<<<2048, 256>>>(ei32, w2, b2, out, E, n_users, n_movies);
}